// round 10
// baseline (speedup 1.0000x reference)
#include <cuda_runtime.h>
#include <mma.h>
#include <math.h>

using namespace nvcuda;

// ConvTranspose2d(64->64,k4,s2,p1)+BN+softmax(ch)+maxpool2x2, tf32 wmma.
// R9: 512 threads (16 warps, 16x32 C-tile each), cp.async double-buffered
// per-tap B staging overlapped with MMA, pair-split epilogue (32 ch/thread).

#define CSTR 68
#define SLAB_F (4 * 66 * CSTR)          // 17952
#define BB_F   (64 * CSTR)              // 4352 per buffer
#define C_F    (128 * CSTR)             // 8704
#define OFF_SLAB 0
#define OFF_B   (OFF_SLAB + SLAB_F)     // 2 buffers
#define OFF_C   (OFF_B + 2 * BB_F)
#define OFF_MP  (OFF_C + C_F)
#define OFF_AB  (OFF_MP + C_F)
#define SMEM_FLOATS (OFF_AB + 128)
#define SMEM_BYTES (SMEM_FLOATS * 4)    // ~177.5 KB

// Pre-transposed, pre-tf32-rounded weights: [class*4+tap][cin][cout]
__device__ float wT[16 * 4096];

__global__ void prep_weights(const float* __restrict__ w) {
    int idx = blockIdx.x * 256 + threadIdx.x;   // 65536
    int ct  = idx >> 12;
    int e   = idx & 4095;
    int cin = e >> 6, co = e & 63;
    int c = ct >> 2, tp = ct & 3;
    int r = c >> 1, b = c & 1, dh = tp >> 1, dw = tp & 1;
    wT[ct * 4096 + cin * 64 + co] =
        wmma::__float_to_tf32(w[(cin * 64 + co) * 16
                                + (3 - r - 2 * dh) * 4 + (3 - b - 2 * dw)]);
}

__device__ __forceinline__ void cp16(unsigned smem_dst, const void* gsrc) {
    asm volatile("cp.async.cg.shared.global [%0], [%1], 16;"
                 :: "r"(smem_dst), "l"(__cvta_generic_to_global(gsrc)));
}
#define CP_COMMIT() asm volatile("cp.async.commit_group;" ::: "memory")
#define CP_WAIT0()  asm volatile("cp.async.wait_group 0;" ::: "memory")

__device__ __forceinline__ unsigned smem_u32(const void* p) {
    unsigned a;
    asm("{ .reg .u64 t; cvta.to.shared.u64 t, %1; cvt.u32.u64 %0, t; }" : "=r"(a) : "l"(p));
    return a;
}

extern __shared__ float sm[];

__global__ __launch_bounds__(512, 1)
void fused_wmma_kernel(const float* __restrict__ x,
                       const float* __restrict__ conv_bias,
                       const float* __restrict__ gamma,
                       const float* __restrict__ beta,
                       const float* __restrict__ rmean,
                       const float* __restrict__ rvar,
                       float* __restrict__ out)
{
    float* slab = sm + OFF_SLAB;   // [srow4][col66][cin CSTR]
    float* Bsm  = sm + OFF_B;      // [2][cin64][cout CSTR]
    float* Cbuf = sm + OFF_C;      // [m128][CSTR]
    float* Mp   = sm + OFF_MP;     // [m128][CSTR]
    float* As   = sm + OFF_AB;
    float* Bs   = As + 64;

    const int t  = threadIdx.x;
    const int pb = blockIdx.x;
    const int n  = blockIdx.y;

    if (t < 64) {
        float a = gamma[t] * rsqrtf(rvar[t] + 1e-5f);
        As[t] = a;
        Bs[t] = (conv_bias[t] - rmean[t]) * a + beta[t];
    }

    // slab: rows ih = 2pb-1 .. 2pb+2, tf32-rounded; layout [srow][iw+1][cin]
    for (int i = t; i < 4 * 64 * 64; i += 512) {
        int iw   = i & 63;
        int cin  = (i >> 6) & 63;
        int srow = i >> 12;
        int ih = 2 * pb - 1 + srow;
        float v = 0.f;
        if ((unsigned)ih < 64u)
            v = x[((n * 64 + cin) * 64 + ih) * 64 + iw];
        slab[(srow * 66 + iw + 1) * CSTR + cin] = wmma::__float_to_tf32(v);
    }
    for (int i = t; i < 4 * 2 * 64; i += 512) {
        int cin  = i & 63;
        int side = (i >> 6) & 1;
        int srow = i >> 7;
        slab[(srow * 66 + (side ? 65 : 0)) * CSTR + cin] = 0.f;
    }

    const unsigned bsm_u[2] = { smem_u32(Bsm), smem_u32(Bsm + BB_F) };

    // prefetch class0/tap0 into buffer 0: 4096 floats = 1024 x 16B
    {
        const float4* src = (const float4*)wT;
        for (int i = t; i < 1024; i += 512) {
            int cin = i >> 4, c4 = i & 15;
            cp16(bsm_u[0] + (cin * CSTR + c4 * 4) * 4, src + i);
        }
        CP_COMMIT();
    }
    CP_WAIT0();
    __syncthreads();

    const int wid = t >> 5;
    const int mi  = wid >> 1;            // 16-row stripe 0..7
    const int ni  = wid & 1;             // 32-col half
    const int pl  = mi >> 2;
    const int qr  = (mi & 3) * 16;       // row (=q) base within half
    const int m0  = mi * 16;

    for (int c = 0; c < 4; ++c) {
        const int r = c >> 1, b = c & 1;

        wmma::fragment<wmma::accumulator, 16, 16, 8, float> fc[2];
        wmma::fill_fragment(fc[0], 0.f);
        wmma::fill_fragment(fc[1], 0.f);

        #pragma unroll
        for (int tap = 0; tap < 4; ++tap) {
            const int buf = tap & 1;
            // prefetch next tile (tap+1, or next class's tap0) into buf^1
            const int nxt = c * 4 + tap + 1;
            if (nxt < 16) {
                const float4* src = (const float4*)(wT + nxt * 4096);
                for (int i = t; i < 1024; i += 512) {
                    int cin = i >> 4, c4 = i & 15;
                    cp16(bsm_u[buf ^ 1] + (cin * CSTR + c4 * 4) * 4, src + i);
                }
            }
            CP_COMMIT();

            const int dh = tap >> 1, dw = tap & 1;
            const float* abase = slab + ((r + pl + dh) * 66 + qr + b + dw) * CSTR;
            const float* bbase = Bsm + buf * BB_F + ni * 32;
            #pragma unroll
            for (int k0 = 0; k0 < 64; k0 += 8) {
                wmma::fragment<wmma::matrix_a, 16, 16, 8,
                               wmma::precision::tf32, wmma::row_major> fa;
                wmma::load_matrix_sync(fa, abase + k0, CSTR);
                #pragma unroll
                for (int nf = 0; nf < 2; ++nf) {
                    wmma::fragment<wmma::matrix_b, 16, 16, 8,
                                   wmma::precision::tf32, wmma::row_major> fb;
                    wmma::load_matrix_sync(fb, bbase + k0 * CSTR + nf * 16, CSTR);
                    wmma::mma_sync(fc[nf], fa, fb, fc[nf]);
                }
            }
            CP_WAIT0();
            __syncthreads();
        }

        wmma::store_matrix_sync(Cbuf + m0 * CSTR + ni * 32, fc[0], CSTR,
                                wmma::mem_row_major);
        wmma::store_matrix_sync(Cbuf + m0 * CSTR + ni * 32 + 16, fc[1], CSTR,
                                wmma::mem_row_major);
        __syncthreads();

        // epilogue: thread pair (2m, 2m+1) -> position m, 32 channels each
        if (t < 256) {
            const int m    = t >> 1;
            const int half = t & 1;
            const int cb   = half * 32;
            float v[32];
            const float* crow = Cbuf + m * CSTR + cb;
            #pragma unroll
            for (int j = 0; j < 32; ++j)
                v[j] = fmaf(crow[j], As[cb + j], Bs[cb + j]);
            float mx = v[0];
            #pragma unroll
            for (int j = 1; j < 32; ++j) mx = fmaxf(mx, v[j]);
            mx = fmaxf(mx, __shfl_xor_sync(0xFFFFFFFFu, mx, 1));
            float s = 0.f;
            #pragma unroll
            for (int j = 0; j < 32; ++j) { v[j] = __expf(v[j] - mx); s += v[j]; }
            s += __shfl_xor_sync(0xFFFFFFFFu, s, 1);
            const float inv = 1.f / s;

            float* mrow = Mp + m * CSTR + cb;
            if (c == 0) {
                #pragma unroll
                for (int j = 0; j < 32; ++j) mrow[j] = v[j] * inv;
            } else if (c < 3) {
                #pragma unroll
                for (int j = 0; j < 32; ++j) mrow[j] = fmaxf(mrow[j], v[j] * inv);
            } else {
                const int po = 2 * pb + (m >> 6);
                const int q  = m & 63;
                #pragma unroll
                for (int j = 0; j < 32; ++j)
                    out[((n * 64 + cb + j) * 64 + po) * 64 + q] =
                        fmaxf(mrow[j], v[j] * inv);
            }
        }
        __syncthreads();
    }
}

extern "C" void kernel_launch(void* const* d_in, const int* in_sizes, int n_in,
                              void* d_out, int out_size)
{
    const float* x         = (const float*)d_in[0];
    const float* w         = (const float*)d_in[1];
    const float* conv_bias = (const float*)d_in[2];
    const float* gamma     = (const float*)d_in[3];
    const float* beta      = (const float*)d_in[4];
    const float* rmean     = (const float*)d_in[5];
    const float* rvar      = (const float*)d_in[6];
    float* out             = (float*)d_out;

    prep_weights<<<256, 256>>>(w);

    cudaFuncSetAttribute(fused_wmma_kernel,
                         cudaFuncAttributeMaxDynamicSharedMemorySize, SMEM_BYTES);
    dim3 grid(32, 32);
    fused_wmma_kernel<<<grid, 512, SMEM_BYTES>>>(
        x, conv_bias, gamma, beta, rmean, rvar, out);
}

// round 11
// speedup vs baseline: 2.0834x; 2.0834x over previous
#include <cuda_runtime.h>
#include <mma.h>
#include <math.h>

using namespace nvcuda;

// ConvTranspose2d(64->64,k4,s2,p1)+BN+softmax(ch)+maxpool2x2, tf32 wmma.
// R10: 16 warps; 32x32 warp C-tiles with K-split (2 taps/warp) into two Cbuf
// halves summed in the epilogue; per-class LDG->STS B staging (L2-resident);
// pool running-max in registers; 3 syncs/class.
//
// Parity decomposition (validated): conv out (oy=2*po+r, ox=2*qo+b), taps
// (dh,dw): ih=po+r+dh-1, iw=qo+b+dw-1, kh=3-r-2dh, kw=3-b-2dw.
// Block (pb,n): per class c=(r,b): C[m=pl*64+q][cout] over K=4taps x 64cin.

#define CSTR 68
#define SLAB_F (4 * 66 * CSTR)          // 17952
#define B_F    (4 * 64 * CSTR)          // 17408
#define C_F    (128 * CSTR)             // 8704
#define OFF_SLAB 0
#define OFF_B   (OFF_SLAB + SLAB_F)
#define OFF_C0  (OFF_B + B_F)
#define OFF_C1  (OFF_C0 + C_F)
#define OFF_AB  (OFF_C1 + C_F)
#define SMEM_FLOATS (OFF_AB + 128)
#define SMEM_BYTES (SMEM_FLOATS * 4)    // 211,584 B

// Pre-transposed, pre-tf32-rounded weights: [class*4+tap][cin][cout]
__device__ float wT[16 * 4096];

__global__ void prep_weights(const float* __restrict__ w) {
    int idx = blockIdx.x * 256 + threadIdx.x;   // 65536
    int ct  = idx >> 12;
    int e   = idx & 4095;
    int cin = e >> 6, co = e & 63;
    int c = ct >> 2, tp = ct & 3;
    int r = c >> 1, b = c & 1, dh = tp >> 1, dw = tp & 1;
    wT[ct * 4096 + cin * 64 + co] =
        wmma::__float_to_tf32(w[(cin * 64 + co) * 16
                                + (3 - r - 2 * dh) * 4 + (3 - b - 2 * dw)]);
}

extern __shared__ float sm[];

__global__ __launch_bounds__(512, 1)
void fused_wmma_kernel(const float* __restrict__ x,
                       const float* __restrict__ conv_bias,
                       const float* __restrict__ gamma,
                       const float* __restrict__ beta,
                       const float* __restrict__ rmean,
                       const float* __restrict__ rvar,
                       float* __restrict__ out)
{
    float* slab = sm + OFF_SLAB;   // [srow4][col66][cin CSTR]
    float* Bsm  = sm + OFF_B;      // [tap4][cin64][cout CSTR]
    float* As   = sm + OFF_AB;
    float* Bs   = As + 64;

    const int t  = threadIdx.x;
    const int pb = blockIdx.x;
    const int n  = blockIdx.y;

    if (t < 64) {
        float a = gamma[t] * rsqrtf(rvar[t] + 1e-5f);
        As[t] = a;
        Bs[t] = (conv_bias[t] - rmean[t]) * a + beta[t];
    }

    // slab: rows ih = 2pb-1 .. 2pb+2, tf32-rounded; layout [srow][iw+1][cin]
    for (int i = t; i < 4 * 64 * 64; i += 512) {
        int iw   = i & 63;
        int cin  = (i >> 6) & 63;
        int srow = i >> 12;
        int ih = 2 * pb - 1 + srow;
        float v = 0.f;
        if ((unsigned)ih < 64u)
            v = x[((n * 64 + cin) * 64 + ih) * 64 + iw];
        slab[(srow * 66 + iw + 1) * CSTR + cin] = wmma::__float_to_tf32(v);
    }
    for (int i = t; i < 4 * 2 * 64; i += 512) {
        int cin  = i & 63;
        int side = (i >> 6) & 1;
        int srow = i >> 7;
        slab[(srow * 66 + (side ? 65 : 0)) * CSTR + cin] = 0.f;
    }

    // warp mapping: kh = K half (2 taps), tile = 32x32 C-subtile
    const int wid  = t >> 5;
    const int kh   = wid & 1;
    const int tile = wid >> 1;       // 0..7
    const int mt   = tile >> 1;      // 32-row group
    const int nt   = tile & 1;       // 32-col group

    // epilogue mapping: quad of lanes per position
    const int em  = t >> 2;          // position m = 0..127
    const int ech = (t & 3) * 16;    // 16-channel chunk
    const int po  = 2 * pb + (em >> 6);
    const int eq  = em & 63;

    float rmax[16];                   // running 2x2-pool max (across classes)

    for (int c = 0; c < 4; ++c) {
        const int r = c >> 1, b = c & 1;

        // stage class-c B (16KB) via LDG->STS (L2-resident wT)
        {
            const float4* src = (const float4*)(wT + c * 16384);
            for (int i = t; i < 4096; i += 512) {
                int row = i >> 4;            // tap*64 + cin
                int c4  = i & 15;
                *(float4*)(Bsm + row * CSTR + c4 * 4) = src[i];
            }
        }
        __syncthreads();

        wmma::fragment<wmma::accumulator, 16, 16, 8, float> fc[2][2];
        #pragma unroll
        for (int s = 0; s < 2; ++s)
            #pragma unroll
            for (int ns = 0; ns < 2; ++ns)
                wmma::fill_fragment(fc[s][ns], 0.f);

        #pragma unroll
        for (int tp = 0; tp < 2; ++tp) {
            const int tap = kh * 2 + tp;
            const int dh = tap >> 1, dw = tap & 1;
            const float* ab[2];
            #pragma unroll
            for (int s = 0; s < 2; ++s) {
                const int ms = 32 * mt + 16 * s;
                ab[s] = slab + ((r + (ms >> 6) + dh) * 66 + (ms & 63) + b + dw) * CSTR;
            }
            const float* bbase = Bsm + tap * 64 * CSTR + nt * 32;
            #pragma unroll
            for (int k0 = 0; k0 < 64; k0 += 8) {
                wmma::fragment<wmma::matrix_b, 16, 16, 8,
                               wmma::precision::tf32, wmma::row_major> fb[2];
                wmma::load_matrix_sync(fb[0], bbase + k0 * CSTR, CSTR);
                wmma::load_matrix_sync(fb[1], bbase + k0 * CSTR + 16, CSTR);
                #pragma unroll
                for (int s = 0; s < 2; ++s) {
                    wmma::fragment<wmma::matrix_a, 16, 16, 8,
                                   wmma::precision::tf32, wmma::row_major> fa;
                    wmma::load_matrix_sync(fa, ab[s] + k0, CSTR);
                    wmma::mma_sync(fc[s][0], fa, fb[0], fc[s][0]);
                    wmma::mma_sync(fc[s][1], fa, fb[1], fc[s][1]);
                }
            }
        }

        float* cdst = sm + (kh ? OFF_C1 : OFF_C0);
        #pragma unroll
        for (int s = 0; s < 2; ++s)
            #pragma unroll
            for (int ns = 0; ns < 2; ++ns)
                wmma::store_matrix_sync(cdst + (32 * mt + 16 * s) * CSTR
                                             + nt * 32 + 16 * ns,
                                        fc[s][ns], CSTR, wmma::mem_row_major);
        __syncthreads();

        // epilogue: combine K halves, BN, softmax (quad shfl), pool max in regs
        {
            const float* c0 = sm + OFF_C0 + em * CSTR + ech;
            const float* c1 = sm + OFF_C1 + em * CSTR + ech;
            float v[16];
            #pragma unroll
            for (int j = 0; j < 16; ++j)
                v[j] = fmaf(c0[j] + c1[j], As[ech + j], Bs[ech + j]);
            float mx = v[0];
            #pragma unroll
            for (int j = 1; j < 16; ++j) mx = fmaxf(mx, v[j]);
            mx = fmaxf(mx, __shfl_xor_sync(0xFFFFFFFFu, mx, 1));
            mx = fmaxf(mx, __shfl_xor_sync(0xFFFFFFFFu, mx, 2));
            float s = 0.f;
            #pragma unroll
            for (int j = 0; j < 16; ++j) { v[j] = __expf(v[j] - mx); s += v[j]; }
            s += __shfl_xor_sync(0xFFFFFFFFu, s, 1);
            s += __shfl_xor_sync(0xFFFFFFFFu, s, 2);
            const float inv = 1.f / s;

            if (c == 0) {
                #pragma unroll
                for (int j = 0; j < 16; ++j) rmax[j] = v[j] * inv;
            } else if (c < 3) {
                #pragma unroll
                for (int j = 0; j < 16; ++j) rmax[j] = fmaxf(rmax[j], v[j] * inv);
            } else {
                #pragma unroll
                for (int j = 0; j < 16; ++j)
                    out[((n * 64 + ech + j) * 64 + po) * 64 + eq] =
                        fmaxf(rmax[j], v[j] * inv);
            }
        }
        __syncthreads();   // protect Bsm/Cbuf overwrite next class
    }
}

extern "C" void kernel_launch(void* const* d_in, const int* in_sizes, int n_in,
                              void* d_out, int out_size)
{
    const float* x         = (const float*)d_in[0];
    const float* w         = (const float*)d_in[1];
    const float* conv_bias = (const float*)d_in[2];
    const float* gamma     = (const float*)d_in[3];
    const float* beta      = (const float*)d_in[4];
    const float* rmean     = (const float*)d_in[5];
    const float* rvar      = (const float*)d_in[6];
    float* out             = (float*)d_out;

    prep_weights<<<256, 256>>>(w);

    cudaFuncSetAttribute(fused_wmma_kernel,
                         cudaFuncAttributeMaxDynamicSharedMemorySize, SMEM_BYTES);
    dim3 grid(32, 32);
    fused_wmma_kernel<<<grid, 512, SMEM_BYTES>>>(
        x, conv_bias, gamma, beta, rmean, rvar, out);
}

// round 12
// speedup vs baseline: 5.1177x; 2.4565x over previous
#include <cuda_runtime.h>
#include <cuda_fp16.h>
#include <mma.h>
#include <math.h>

using namespace nvcuda;

// ConvTranspose2d(64->64,k4,s2,p1)+BN+softmax(ch)+maxpool2x2, fp16 wmma k16.
// R11: fp16 A/B storage (same 11-bit significand as tf32; products exact in
// f32 accum), m16n16k16 MMA (2x K/instr), ALL 16 (class,tap) B tiles staged
// once per block, 16 warps = 8 M-stripes x 2 N-halves, single f32 Cbuf.
//
// Parity decomposition (validated): conv out (oy=2*po+r, ox=2*qo+b), taps
// (dh,dw): ih=po+r+dh-1, iw=qo+b+dw-1, kh=3-r-2dh, kw=3-b-2dw.
// Block (pb,n): per class c=(r,b): C[m=pl*64+q][cout], K = 4taps x 64cin.

#define SSTR 72                          // slab inner stride (halves), 144B rows
#define BSTR 72                          // B row stride (halves)
#define CSTR 68                          // Cbuf row stride (floats)
#define SLAB_H (4 * 66 * SSTR)           // 19008 halves = 38016 B
#define BALL_H (16 * 64 * BSTR)          // 73728 halves = 147456 B
#define C_F    (128 * CSTR)              // 8704 floats = 34816 B
#define OFF_SLAB 0
#define OFF_B    (OFF_SLAB + SLAB_H * 2)             // bytes
#define OFF_C    (OFF_B + BALL_H * 2)
#define OFF_AB   (OFF_C + C_F * 4)
#define SMEM_BYTES (OFF_AB + 128 * 4)    // 220,800 B

// Pre-transposed fp16 weights: [class*4+tap][cin][cout], 16B-aligned
__device__ __align__(16) __half wTh[16 * 4096];

__global__ void prep_weights(const float* __restrict__ w) {
    int idx = blockIdx.x * 256 + threadIdx.x;   // 65536
    int ct  = idx >> 12;
    int e   = idx & 4095;
    int cin = e >> 6, co = e & 63;
    int c = ct >> 2, tp = ct & 3;
    int r = c >> 1, b = c & 1, dh = tp >> 1, dw = tp & 1;
    wTh[ct * 4096 + cin * 64 + co] =
        __float2half_rn(w[(cin * 64 + co) * 16
                          + (3 - r - 2 * dh) * 4 + (3 - b - 2 * dw)]);
}

extern __shared__ char smraw[];

__global__ __launch_bounds__(512, 1)
void fused_wmma_kernel(const float* __restrict__ x,
                       const float* __restrict__ conv_bias,
                       const float* __restrict__ gamma,
                       const float* __restrict__ beta,
                       const float* __restrict__ rmean,
                       const float* __restrict__ rvar,
                       float* __restrict__ out)
{
    __half* slab = (__half*)(smraw + OFF_SLAB);  // [srow4][col66][cin SSTR]
    __half* Bsm  = (__half*)(smraw + OFF_B);     // [ct16][cin64][BSTR]
    float*  Cbuf = (float*)(smraw + OFF_C);      // [m128][CSTR]
    float*  As   = (float*)(smraw + OFF_AB);
    float*  Bs   = As + 64;

    const int t  = threadIdx.x;
    const int pb = blockIdx.x;
    const int n  = blockIdx.y;

    if (t < 64) {
        float a = gamma[t] * rsqrtf(rvar[t] + 1e-5f);
        As[t] = a;
        Bs[t] = (conv_bias[t] - rmean[t]) * a + beta[t];
    }

    // slab: rows ih = 2pb-1 .. 2pb+2, fp16; layout [srow][iw+1][cin]
    for (int i = t; i < 4 * 64 * 64; i += 512) {
        int iw   = i & 63;
        int cin  = (i >> 6) & 63;
        int srow = i >> 12;
        int ih = 2 * pb - 1 + srow;
        float v = 0.f;
        if ((unsigned)ih < 64u)
            v = x[((n * 64 + cin) * 64 + ih) * 64 + iw];
        slab[(srow * 66 + iw + 1) * SSTR + cin] = __float2half_rn(v);
    }
    for (int i = t; i < 4 * 2 * 64; i += 512) {
        int cin  = i & 63;
        int side = (i >> 6) & 1;
        int srow = i >> 7;
        slab[(srow * 66 + (side ? 65 : 0)) * SSTR + cin] = __half(0.f);
    }

    // stage ALL B tiles once: 131072 B = 8192 float4; row = ct*64+cin (1024
    // rows of 64 halves = 8 chunks of 8 halves = 8 float4)
    {
        const float4* src = (const float4*)wTh;
        for (int i = t; i < 8192; i += 512) {
            int row = i >> 3;
            int ch  = i & 7;
            *(float4*)(Bsm + row * BSTR + ch * 8) = src[i];
        }
    }
    __syncthreads();

    // warp mapping: 8 M-stripes x 2 N-halves
    const int wid = t >> 5;
    const int mt  = wid >> 1;         // stripe: rows m0..m0+15
    const int nt  = wid & 1;          // 32-col half
    const int m0  = mt * 16;
    const int pl  = m0 >> 6;
    const int q0  = m0 & 63;

    // epilogue mapping: quad of lanes per position
    const int em  = t >> 2;
    const int ech = (t & 3) * 16;
    const int po  = 2 * pb + (em >> 6);
    const int eq  = em & 63;

    float rmax[16];

    for (int c = 0; c < 4; ++c) {
        const int r = c >> 1, b = c & 1;

        wmma::fragment<wmma::accumulator, 16, 16, 16, float> fc[2];
        wmma::fill_fragment(fc[0], 0.f);
        wmma::fill_fragment(fc[1], 0.f);

        #pragma unroll
        for (int tap = 0; tap < 4; ++tap) {
            const int dh = tap >> 1, dw = tap & 1;
            const __half* abase =
                slab + ((r + pl + dh) * 66 + q0 + b + dw) * SSTR;
            const __half* bbase =
                Bsm + ((c * 4 + tap) * 64) * BSTR + nt * 32;
            #pragma unroll
            for (int k0 = 0; k0 < 64; k0 += 16) {
                wmma::fragment<wmma::matrix_a, 16, 16, 16, __half,
                               wmma::row_major> fa;
                wmma::load_matrix_sync(fa, abase + k0, SSTR);
                wmma::fragment<wmma::matrix_b, 16, 16, 16, __half,
                               wmma::row_major> fb0, fb1;
                wmma::load_matrix_sync(fb0, bbase + k0 * BSTR, BSTR);
                wmma::load_matrix_sync(fb1, bbase + k0 * BSTR + 16, BSTR);
                wmma::mma_sync(fc[0], fa, fb0, fc[0]);
                wmma::mma_sync(fc[1], fa, fb1, fc[1]);
            }
        }

        wmma::store_matrix_sync(Cbuf + m0 * CSTR + nt * 32, fc[0], CSTR,
                                wmma::mem_row_major);
        wmma::store_matrix_sync(Cbuf + m0 * CSTR + nt * 32 + 16, fc[1], CSTR,
                                wmma::mem_row_major);
        __syncthreads();

        // epilogue: BN, softmax (quad shfl), pool running-max in registers
        {
            const float* crow = Cbuf + em * CSTR + ech;
            float v[16];
            #pragma unroll
            for (int j = 0; j < 16; ++j)
                v[j] = fmaf(crow[j], As[ech + j], Bs[ech + j]);
            float mx = v[0];
            #pragma unroll
            for (int j = 1; j < 16; ++j) mx = fmaxf(mx, v[j]);
            mx = fmaxf(mx, __shfl_xor_sync(0xFFFFFFFFu, mx, 1));
            mx = fmaxf(mx, __shfl_xor_sync(0xFFFFFFFFu, mx, 2));
            float s = 0.f;
            #pragma unroll
            for (int j = 0; j < 16; ++j) { v[j] = __expf(v[j] - mx); s += v[j]; }
            s += __shfl_xor_sync(0xFFFFFFFFu, s, 1);
            s += __shfl_xor_sync(0xFFFFFFFFu, s, 2);
            const float inv = 1.f / s;

            if (c == 0) {
                #pragma unroll
                for (int j = 0; j < 16; ++j) rmax[j] = v[j] * inv;
            } else if (c < 3) {
                #pragma unroll
                for (int j = 0; j < 16; ++j) rmax[j] = fmaxf(rmax[j], v[j] * inv);
            } else {
                #pragma unroll
                for (int j = 0; j < 16; ++j)
                    out[((n * 64 + ech + j) * 64 + po) * 64 + eq] =
                        fmaxf(rmax[j], v[j] * inv);
            }
        }
        __syncthreads();   // Cbuf reused next class
    }
}

extern "C" void kernel_launch(void* const* d_in, const int* in_sizes, int n_in,
                              void* d_out, int out_size)
{
    const float* x         = (const float*)d_in[0];
    const float* w         = (const float*)d_in[1];
    const float* conv_bias = (const float*)d_in[2];
    const float* gamma     = (const float*)d_in[3];
    const float* beta      = (const float*)d_in[4];
    const float* rmean     = (const float*)d_in[5];
    const float* rvar      = (const float*)d_in[6];
    float* out             = (float*)d_out;

    prep_weights<<<256, 256>>>(w);

    cudaFuncSetAttribute(fused_wmma_kernel,
                         cudaFuncAttributeMaxDynamicSharedMemorySize, SMEM_BYTES);
    dim3 grid(32, 32);
    fused_wmma_kernel<<<grid, 512, SMEM_BYTES>>>(
        x, conv_bias, gamma, beta, rmean, rvar, out);
}

// round 13
// speedup vs baseline: 5.8544x; 1.1440x over previous
#include <cuda_runtime.h>
#include <cuda_fp16.h>
#include <mma.h>
#include <math.h>

using namespace nvcuda;

// ConvTranspose2d(64->64,k4,s2,p1)+BN+softmax(ch)+maxpool2x2, fp16 wmma k16.
// R12: per-class B staging (36.9KB) cuts smem 220.8K -> 110.2K => 2 CTAs/SM
// (8 warps/SMSP), fixing the occupancy-bound signature (occ 25%, issue 26%).
// Co-resident CTAs phase-shift to cover each other's sync/staging bubbles.
//
// Parity decomposition (validated): conv out (oy=2*po+r, ox=2*qo+b), taps
// (dh,dw): ih=po+r+dh-1, iw=qo+b+dw-1, kh=3-r-2dh, kw=3-b-2dw.
// Block (pb,n): per class c=(r,b): C[m=pl*64+q][cout], K = 4taps x 64cin.

#define SSTR 72                          // slab inner stride (halves)
#define BSTR 72                          // B row stride (halves)
#define CSTR 68                          // Cbuf row stride (floats)
#define SLAB_H (4 * 66 * SSTR)           // 19008 halves = 38016 B
#define B_H    (4 * 64 * BSTR)           // 18432 halves = 36864 B
#define C_F    (128 * CSTR)              // 8704 floats  = 34816 B
#define OFF_SLAB 0
#define OFF_B    (OFF_SLAB + SLAB_H * 2)
#define OFF_C    (OFF_B + B_H * 2)
#define OFF_AB   (OFF_C + C_F * 4)
#define SMEM_BYTES (OFF_AB + 128 * 4)    // 110,208 B -> 2 CTAs/SM

// Pre-transposed fp16 weights: [class*4+tap][cin][cout], 16B-aligned
__device__ __align__(16) __half wTh[16 * 4096];

__global__ void prep_weights(const float* __restrict__ w) {
    int idx = blockIdx.x * 256 + threadIdx.x;   // 65536
    int ct  = idx >> 12;
    int e   = idx & 4095;
    int cin = e >> 6, co = e & 63;
    int c = ct >> 2, tp = ct & 3;
    int r = c >> 1, b = c & 1, dh = tp >> 1, dw = tp & 1;
    wTh[ct * 4096 + cin * 64 + co] =
        __float2half_rn(w[(cin * 64 + co) * 16
                          + (3 - r - 2 * dh) * 4 + (3 - b - 2 * dw)]);
}

extern __shared__ char smraw[];

__global__ __launch_bounds__(512, 2)
void fused_wmma_kernel(const float* __restrict__ x,
                       const float* __restrict__ conv_bias,
                       const float* __restrict__ gamma,
                       const float* __restrict__ beta,
                       const float* __restrict__ rmean,
                       const float* __restrict__ rvar,
                       float* __restrict__ out)
{
    __half* slab = (__half*)(smraw + OFF_SLAB);  // [srow4][col66][cin SSTR]
    __half* Bsm  = (__half*)(smraw + OFF_B);     // [tap4*cin64][BSTR]
    float*  Cbuf = (float*)(smraw + OFF_C);      // [m128][CSTR]
    float*  As   = (float*)(smraw + OFF_AB);
    float*  Bs   = As + 64;

    const int t  = threadIdx.x;
    const int pb = blockIdx.x;
    const int n  = blockIdx.y;

    if (t < 64) {
        float a = gamma[t] * rsqrtf(rvar[t] + 1e-5f);
        As[t] = a;
        Bs[t] = (conv_bias[t] - rmean[t]) * a + beta[t];
    }

    // slab: rows ih = 2pb-1 .. 2pb+2, fp16; layout [srow][iw+1][cin]
    for (int i = t; i < 4 * 64 * 64; i += 512) {
        int iw   = i & 63;
        int cin  = (i >> 6) & 63;
        int srow = i >> 12;
        int ih = 2 * pb - 1 + srow;
        float v = 0.f;
        if ((unsigned)ih < 64u)
            v = x[((n * 64 + cin) * 64 + ih) * 64 + iw];
        slab[(srow * 66 + iw + 1) * SSTR + cin] = __float2half_rn(v);
    }
    for (int i = t; i < 4 * 2 * 64; i += 512) {
        int cin  = i & 63;
        int side = (i >> 6) & 1;
        int srow = i >> 7;
        slab[(srow * 66 + (side ? 65 : 0)) * SSTR + cin] = __half(0.f);
    }

    // warp mapping: 8 M-stripes x 2 N-halves
    const int wid = t >> 5;
    const int mt  = wid >> 1;
    const int nt  = wid & 1;
    const int m0  = mt * 16;
    const int pl  = m0 >> 6;
    const int q0  = m0 & 63;

    // epilogue mapping: quad of lanes per position
    const int em  = t >> 2;
    const int ech = (t & 3) * 16;
    const int po  = 2 * pb + (em >> 6);
    const int eq  = em & 63;

    float rmax[16];

    for (int c = 0; c < 4; ++c) {
        const int r = c >> 1, b = c & 1;

        // stage class-c B: 32KB = 2048 float4; row = tap*64+cin (64 halves
        // = 8 float4 chunks per row)
        {
            const float4* src = (const float4*)(wTh + c * 16384);
            for (int i = t; i < 2048; i += 512) {
                int row = i >> 3;
                int ch  = i & 7;
                *(float4*)(Bsm + row * BSTR + ch * 8) = src[i];
            }
        }
        __syncthreads();

        wmma::fragment<wmma::accumulator, 16, 16, 16, float> fc[2];
        wmma::fill_fragment(fc[0], 0.f);
        wmma::fill_fragment(fc[1], 0.f);

        #pragma unroll
        for (int tap = 0; tap < 4; ++tap) {
            const int dh = tap >> 1, dw = tap & 1;
            const __half* abase =
                slab + ((r + pl + dh) * 66 + q0 + b + dw) * SSTR;
            const __half* bbase = Bsm + (tap * 64) * BSTR + nt * 32;
            #pragma unroll
            for (int k0 = 0; k0 < 64; k0 += 16) {
                wmma::fragment<wmma::matrix_a, 16, 16, 16, __half,
                               wmma::row_major> fa;
                wmma::load_matrix_sync(fa, abase + k0, SSTR);
                wmma::fragment<wmma::matrix_b, 16, 16, 16, __half,
                               wmma::row_major> fb0, fb1;
                wmma::load_matrix_sync(fb0, bbase + k0 * BSTR, BSTR);
                wmma::load_matrix_sync(fb1, bbase + k0 * BSTR + 16, BSTR);
                wmma::mma_sync(fc[0], fa, fb0, fc[0]);
                wmma::mma_sync(fc[1], fa, fb1, fc[1]);
            }
        }

        wmma::store_matrix_sync(Cbuf + m0 * CSTR + nt * 32, fc[0], CSTR,
                                wmma::mem_row_major);
        wmma::store_matrix_sync(Cbuf + m0 * CSTR + nt * 32 + 16, fc[1], CSTR,
                                wmma::mem_row_major);
        __syncthreads();

        // epilogue: BN, softmax (quad shfl), pool running-max in registers
        {
            const float* crow = Cbuf + em * CSTR + ech;
            float v[16];
            #pragma unroll
            for (int j = 0; j < 16; ++j)
                v[j] = fmaf(crow[j], As[ech + j], Bs[ech + j]);
            float mx = v[0];
            #pragma unroll
            for (int j = 1; j < 16; ++j) mx = fmaxf(mx, v[j]);
            mx = fmaxf(mx, __shfl_xor_sync(0xFFFFFFFFu, mx, 1));
            mx = fmaxf(mx, __shfl_xor_sync(0xFFFFFFFFu, mx, 2));
            float s = 0.f;
            #pragma unroll
            for (int j = 0; j < 16; ++j) { v[j] = __expf(v[j] - mx); s += v[j]; }
            s += __shfl_xor_sync(0xFFFFFFFFu, s, 1);
            s += __shfl_xor_sync(0xFFFFFFFFu, s, 2);
            const float inv = 1.f / s;

            if (c == 0) {
                #pragma unroll
                for (int j = 0; j < 16; ++j) rmax[j] = v[j] * inv;
            } else if (c < 3) {
                #pragma unroll
                for (int j = 0; j < 16; ++j) rmax[j] = fmaxf(rmax[j], v[j] * inv);
            } else {
                #pragma unroll
                for (int j = 0; j < 16; ++j)
                    out[((n * 64 + ech + j) * 64 + po) * 64 + eq] =
                        fmaxf(rmax[j], v[j] * inv);
            }
        }
        __syncthreads();   // Bsm/Cbuf reused next class
    }
}

extern "C" void kernel_launch(void* const* d_in, const int* in_sizes, int n_in,
                              void* d_out, int out_size)
{
    const float* x         = (const float*)d_in[0];
    const float* w         = (const float*)d_in[1];
    const float* conv_bias = (const float*)d_in[2];
    const float* gamma     = (const float*)d_in[3];
    const float* beta      = (const float*)d_in[4];
    const float* rmean     = (const float*)d_in[5];
    const float* rvar      = (const float*)d_in[6];
    float* out             = (float*)d_out;

    prep_weights<<<256, 256>>>(w);

    cudaFuncSetAttribute(fused_wmma_kernel,
                         cudaFuncAttributeMaxDynamicSharedMemorySize, SMEM_BYTES);
    dim3 grid(32, 32);
    fused_wmma_kernel<<<grid, 512, SMEM_BYTES>>>(
        x, conv_bias, gamma, beta, rmean, rvar, out);
}

// round 14
// speedup vs baseline: 7.2483x; 1.2381x over previous
#include <cuda_runtime.h>
#include <cuda_fp16.h>
#include <math.h>

// ConvTranspose2d(64->64,k4,s2,p1)+BN+softmax(ch)+maxpool2x2.
// R13: explicit ldmatrix + mma.sync.m16n8k16 (documented fragment layouts)
// -> fully register-resident epilogue (no Cbuf smem bounce), BN folded into
// weights (scale) and accumulator init (bias), flash-style softmax with
// quad-shfl partials + 2KB cross-warp exchange, pool running-max in half2.
//
// Parity decomposition (validated): conv out (oy=2*po+r, ox=2*qo+b), taps
// (dh,dw): ih=po+r+dh-1, iw=qo+b+dw-1, kh=3-r-2dh, kw=3-b-2dw.
// Block (pb,n): per class c=(r,b): C[m=pl*64+q][cout], K = 4taps x 64cin.
// Warp tile: 16 rows (mt) x 32 cols (nt), 16 warps, 2 CTAs/SM.

#define SSTR 72                       // slab row stride (halves): +4-bank rows
#define BSTR 72                       // B row stride (halves)
#define OFF_SLAB 0
#define OFF_B    38016                // slab = 4*66*72*2
#define OFF_PART 74880                // B = 4*64*72*2
#define SMEM_BYTES 76928              // + part 2KB  -> 2 CTAs/SM

// Pre-transposed fp16 weights, BN scale folded: [class*4+tap][cin][cout]
__device__ __align__(16) __half wTh[16 * 4096];

__global__ void prep_weights(const float* __restrict__ w,
                             const float* __restrict__ gamma,
                             const float* __restrict__ rvar) {
    int idx = blockIdx.x * 256 + threadIdx.x;   // 65536
    int ct  = idx >> 12;
    int e   = idx & 4095;
    int cin = e >> 6, co = e & 63;
    int c = ct >> 2, tp = ct & 3;
    int r = c >> 1, b = c & 1, dh = tp >> 1, dw = tp & 1;
    float scale = gamma[co] * rsqrtf(rvar[co] + 1e-5f);
    wTh[ct * 4096 + cin * 64 + co] =
        __float2half_rn(w[(cin * 64 + co) * 16
                          + (3 - r - 2 * dh) * 4 + (3 - b - 2 * dw)] * scale);
}

__device__ __forceinline__ unsigned smem_u32(const void* p) {
    unsigned a;
    asm("{ .reg .u64 t; cvta.to.shared.u64 t, %1; cvt.u32.u64 %0, t; }"
        : "=r"(a) : "l"(p));
    return a;
}

#define LDSM4(r0, r1, r2, r3, addr) \
    asm volatile("ldmatrix.sync.aligned.m8n8.x4.shared.b16 {%0,%1,%2,%3}, [%4];" \
                 : "=r"(r0), "=r"(r1), "=r"(r2), "=r"(r3) : "r"(addr))
#define LDSM4T(r0, r1, r2, r3, addr) \
    asm volatile("ldmatrix.sync.aligned.m8n8.x4.trans.shared.b16 {%0,%1,%2,%3}, [%4];" \
                 : "=r"(r0), "=r"(r1), "=r"(r2), "=r"(r3) : "r"(addr))
#define MMA16816(d, a0, a1, a2, a3, b0, b1) \
    asm volatile("mma.sync.aligned.m16n8k16.row.col.f32.f16.f16.f32 " \
                 "{%0,%1,%2,%3},{%4,%5,%6,%7},{%8,%9},{%0,%1,%2,%3};" \
                 : "+f"((d)[0]), "+f"((d)[1]), "+f"((d)[2]), "+f"((d)[3]) \
                 : "r"(a0), "r"(a1), "r"(a2), "r"(a3), "r"(b0), "r"(b1))

extern __shared__ char smraw[];

__global__ __launch_bounds__(512, 2)
void fused_mma_kernel(const float* __restrict__ x,
                      const float* __restrict__ conv_bias,
                      const float* __restrict__ gamma,
                      const float* __restrict__ beta,
                      const float* __restrict__ rmean,
                      const float* __restrict__ rvar,
                      float* __restrict__ out)
{
    __half*  slab = (__half*)(smraw + OFF_SLAB);   // [srow4][col66][SSTR]
    __half*  Bsm  = (__half*)(smraw + OFF_B);      // [tap4*64][BSTR]
    float2*  part = (float2*)(smraw + OFF_PART);   // [mt8][nt2][row16]

    const int t  = threadIdx.x;
    const int pb = blockIdx.x;
    const int n  = blockIdx.y;
    const int lane = t & 31, wid = t >> 5;
    const int g = lane >> 2, tig = lane & 3;
    const int mt = wid >> 1, nt = wid & 1;
    const int m0 = mt * 16;
    const int pl = mt >> 2;
    const int q0 = (mt & 3) * 16;

    // per-lane bias (BN-folded) for its 8 columns
    float Bs8[8];
    #pragma unroll
    for (int nf = 0; nf < 4; ++nf)
        #pragma unroll
        for (int j = 0; j < 2; ++j) {
            int col = nt * 32 + nf * 8 + 2 * tig + j;
            float a = gamma[col] * rsqrtf(rvar[col] + 1e-5f);
            Bs8[nf * 2 + j] = (conv_bias[col] - rmean[col]) * a + beta[col];
        }

    // slab: rows ih = 2pb-1 .. 2pb+2; layout [srow][iw+1][cin]
    for (int i = t; i < 4 * 64 * 64; i += 512) {
        int iw   = i & 63;
        int cin  = (i >> 6) & 63;
        int srow = i >> 12;
        int ih = 2 * pb - 1 + srow;
        float v = 0.f;
        if ((unsigned)ih < 64u)
            v = x[((n * 64 + cin) * 64 + ih) * 64 + iw];
        slab[(srow * 66 + iw + 1) * SSTR + cin] = __float2half_rn(v);
    }
    {   // halo cols 0 and 65 (512 entries, one per thread)
        int cin  = t & 63;
        int side = (t >> 6) & 1;
        int srow = t >> 7;
        slab[(srow * 66 + (side ? 65 : 0)) * SSTR + cin] = __float2half_rn(0.f);
    }

    const unsigned slabU = smem_u32(slab);
    const unsigned bsmU  = smem_u32(Bsm);
    // ldmatrix lane address components (canonical x4 patterns)
    const int arow  = ((lane >> 3) & 1) * 8 + (lane & 7);   // row within 16
    const int akofs = (lane >> 4) * 8;                      // k offset 0/8

    __half2 rmax2[8];

    for (int c = 0; c < 4; ++c) {
        const int r = c >> 1, b = c & 1;

        __syncthreads();   // prev mainloop done with Bsm / part read done
        {   // stage class-c B (32KB): row = tap*64+cin, 8 float4 chunks/row
            const float4* src = (const float4*)(wTh + c * 16384);
            #pragma unroll
            for (int i = t; i < 2048; i += 512) {
                int row = i >> 3;
                int ch  = i & 7;
                *(float4*)(Bsm + row * BSTR + ch * 8) = src[i];
            }
        }
        __syncthreads();

        // accumulators init = bias (4 n8-frags x 4 regs)
        float d[4][4];
        #pragma unroll
        for (int nf = 0; nf < 4; ++nf) {
            d[nf][0] = Bs8[2 * nf];     d[nf][1] = Bs8[2 * nf + 1];
            d[nf][2] = Bs8[2 * nf];     d[nf][3] = Bs8[2 * nf + 1];
        }

        #pragma unroll
        for (int tap = 0; tap < 4; ++tap) {
            const int dh = tap >> 1, dw = tap & 1;
            const unsigned aAddr = slabU +
                (((r + pl + dh) * 66 + q0 + arow + b + dw) * SSTR + akofs) * 2;
            const unsigned bAddr = bsmU +
                ((tap * 64 + arow) * BSTR + nt * 32 + akofs) * 2;
            #pragma unroll
            for (int ks = 0; ks < 4; ++ks) {
                unsigned a0, a1, a2, a3, b0, b1, b2, b3;
                LDSM4(a0, a1, a2, a3, aAddr + ks * 32);
                LDSM4T(b0, b1, b2, b3, bAddr + ks * (16 * BSTR * 2));
                MMA16816(d[0], a0, a1, a2, a3, b0, b1);
                MMA16816(d[1], a0, a1, a2, a3, b2, b3);
                LDSM4T(b0, b1, b2, b3, bAddr + ks * (16 * BSTR * 2) + 32);
                MMA16816(d[2], a0, a1, a2, a3, b0, b1);
                MMA16816(d[3], a0, a1, a2, a3, b2, b3);
            }
        }

        // softmax partials over this warp's 32 cols (rows g and g+8)
        float mxlo = d[0][0], mxhi = d[0][2];
        #pragma unroll
        for (int nf = 0; nf < 4; ++nf) {
            mxlo = fmaxf(mxlo, fmaxf(d[nf][0], d[nf][1]));
            mxhi = fmaxf(mxhi, fmaxf(d[nf][2], d[nf][3]));
        }
        mxlo = fmaxf(mxlo, __shfl_xor_sync(0xFFFFFFFFu, mxlo, 1));
        mxlo = fmaxf(mxlo, __shfl_xor_sync(0xFFFFFFFFu, mxlo, 2));
        mxhi = fmaxf(mxhi, __shfl_xor_sync(0xFFFFFFFFu, mxhi, 1));
        mxhi = fmaxf(mxhi, __shfl_xor_sync(0xFFFFFFFFu, mxhi, 2));
        float smlo = 0.f, smhi = 0.f;
        #pragma unroll
        for (int nf = 0; nf < 4; ++nf) {
            float e0 = __expf(d[nf][0] - mxlo); d[nf][0] = e0; smlo += e0;
            float e1 = __expf(d[nf][1] - mxlo); d[nf][1] = e1; smlo += e1;
            float e2 = __expf(d[nf][2] - mxhi); d[nf][2] = e2; smhi += e2;
            float e3 = __expf(d[nf][3] - mxhi); d[nf][3] = e3; smhi += e3;
        }
        smlo += __shfl_xor_sync(0xFFFFFFFFu, smlo, 1);
        smlo += __shfl_xor_sync(0xFFFFFFFFu, smlo, 2);
        smhi += __shfl_xor_sync(0xFFFFFFFFu, smhi, 1);
        smhi += __shfl_xor_sync(0xFFFFFFFFu, smhi, 2);

        if (tig == 0) {
            part[(mt * 2 + nt) * 16 + g]     = make_float2(mxlo, smlo);
            part[(mt * 2 + nt) * 16 + 8 + g] = make_float2(mxhi, smhi);
        }
        __syncthreads();
        const float2 plo = part[(mt * 2 + (nt ^ 1)) * 16 + g];
        const float2 phi = part[(mt * 2 + (nt ^ 1)) * 16 + 8 + g];
        const float Mlo = fmaxf(mxlo, plo.x);
        const float Mhi = fmaxf(mxhi, phi.x);
        const float elo = __expf(mxlo - Mlo);
        const float ehi = __expf(mxhi - Mhi);
        const float sclo = elo / (smlo * elo + plo.y * __expf(plo.x - Mlo));
        const float schi = ehi / (smhi * ehi + phi.y * __expf(phi.x - Mhi));

        if (c == 0) {
            #pragma unroll
            for (int nf = 0; nf < 4; ++nf) {
                rmax2[nf]     = __floats2half2_rn(d[nf][0] * sclo, d[nf][1] * sclo);
                rmax2[4 + nf] = __floats2half2_rn(d[nf][2] * schi, d[nf][3] * schi);
            }
        } else if (c < 3) {
            #pragma unroll
            for (int nf = 0; nf < 4; ++nf) {
                rmax2[nf]     = __hmax2(rmax2[nf],
                    __floats2half2_rn(d[nf][0] * sclo, d[nf][1] * sclo));
                rmax2[4 + nf] = __hmax2(rmax2[4 + nf],
                    __floats2half2_rn(d[nf][2] * schi, d[nf][3] * schi));
            }
        } else {
            const int mlo = m0 + g,  mhi = m0 + 8 + g;
            const int polo = 2 * pb + (mlo >> 6), qlo = mlo & 63;
            const int pohi = 2 * pb + (mhi >> 6), qhi = mhi & 63;
            #pragma unroll
            for (int nf = 0; nf < 4; ++nf) {
                const int col0 = nt * 32 + nf * 8 + 2 * tig;
                float r0 = fmaxf(__low2float(rmax2[nf]),      d[nf][0] * sclo);
                float r1 = fmaxf(__high2float(rmax2[nf]),     d[nf][1] * sclo);
                float r2 = fmaxf(__low2float(rmax2[4 + nf]),  d[nf][2] * schi);
                float r3 = fmaxf(__high2float(rmax2[4 + nf]), d[nf][3] * schi);
                out[((n * 64 + col0)     * 64 + polo) * 64 + qlo] = r0;
                out[((n * 64 + col0 + 1) * 64 + polo) * 64 + qlo] = r1;
                out[((n * 64 + col0)     * 64 + pohi) * 64 + qhi] = r2;
                out[((n * 64 + col0 + 1) * 64 + pohi) * 64 + qhi] = r3;
            }
        }
    }
}

extern "C" void kernel_launch(void* const* d_in, const int* in_sizes, int n_in,
                              void* d_out, int out_size)
{
    const float* x         = (const float*)d_in[0];
    const float* w         = (const float*)d_in[1];
    const float* conv_bias = (const float*)d_in[2];
    const float* gamma     = (const float*)d_in[3];
    const float* beta      = (const float*)d_in[4];
    const float* rmean     = (const float*)d_in[5];
    const float* rvar      = (const float*)d_in[6];
    float* out             = (float*)d_out;

    prep_weights<<<256, 256>>>(w, gamma, rvar);

    cudaFuncSetAttribute(fused_mma_kernel,
                         cudaFuncAttributeMaxDynamicSharedMemorySize, SMEM_BYTES);
    dim3 grid(32, 32);
    fused_mma_kernel<<<grid, 512, SMEM_BYTES>>>(
        x, conv_bias, gamma, beta, rmean, rvar, out);
}